// round 2
// baseline (speedup 1.0000x reference)
#include <cuda_runtime.h>
#include <math.h>

#define NN 20000
#define NE 320000
#define HID 256
#define NG  64

// ---- scratch (device globals; no allocation allowed) ----
__device__ __align__(16) float g_h  [NN * HID];
__device__ __align__(16) float g_agg[NN * HID];
__device__ __align__(16) float g_t  [NN * HID];
__device__ __align__(16) float g_pool[NG * HID];
__device__ __align__(16) float g_cnt[NG];

__device__ __forceinline__ void red_add_v4(float* addr, float4 v) {
    asm volatile("red.global.add.v4.f32 [%0], {%1,%2,%3,%4};"
                 :: "l"(addr), "f"(v.x), "f"(v.y), "f"(v.z), "f"(v.w)
                 : "memory");
}

__global__ void zero4(float4* p, int n4) {
    int i = blockIdx.x * blockDim.x + threadIdx.x;
    if (i < n4) p[i] = make_float4(0.f, 0.f, 0.f, 0.f);
}

// ---------------------------------------------------------------------------
// Generic 128x128 tile SGEMM, N fixed to 256.
//   C[M,256] = act( (A (+A2)) [M,K] @ W[K,256] + bias )
// EDGE variant: instead of writing C, per output row r (an edge):
//   msg = relu(acc + bias + h[src[r]]);  red.add.v4 into agg[dst[r]]
// ---------------------------------------------------------------------------
template<bool RELU, bool HAS_A2, bool EDGE>
__global__ __launch_bounds__(256)
void gemm128(const float* __restrict__ A, const float* __restrict__ A2,
             const float* __restrict__ W, const float* __restrict__ bias,
             float* __restrict__ C,
             const int* __restrict__ ei,
             const float* __restrict__ hg,
             float* __restrict__ agg,
             int M, int K)
{
    __shared__ float As[8][128];
    __shared__ float Bs[8][128];

    const int tid = threadIdx.x;
    const int tx = tid & 15;        // 0..15 -> cols
    const int ty = tid >> 4;        // 0..15 -> rows
    const int rowTile = blockIdx.y * 128;
    const int colTile = blockIdx.x * 128;

    float acc[8][8];
    #pragma unroll
    for (int i = 0; i < 8; i++)
        #pragma unroll
        for (int j = 0; j < 8; j++) acc[i][j] = 0.f;

    const int aRow = tid >> 1;          // 0..127
    const int aCol = (tid & 1) << 2;    // 0 or 4
    const int bRow = tid >> 5;          // 0..7
    const int bCol = (tid & 31) << 2;   // 0..124

    for (int k0 = 0; k0 < K; k0 += 8) {
        float4 av = make_float4(0.f, 0.f, 0.f, 0.f);
        const int gr = rowTile + aRow;
        if (gr < M) {
            av = *reinterpret_cast<const float4*>(A + (size_t)gr * K + k0 + aCol);
            if (HAS_A2) {
                float4 a2 = *reinterpret_cast<const float4*>(A2 + (size_t)gr * K + k0 + aCol);
                av.x += a2.x; av.y += a2.y; av.z += a2.z; av.w += a2.w;
            }
        }
        As[aCol + 0][aRow] = av.x;
        As[aCol + 1][aRow] = av.y;
        As[aCol + 2][aRow] = av.z;
        As[aCol + 3][aRow] = av.w;

        *reinterpret_cast<float4*>(&Bs[bRow][bCol]) =
            *reinterpret_cast<const float4*>(W + (size_t)(k0 + bRow) * 256 + colTile + bCol);

        __syncthreads();

        #pragma unroll
        for (int k = 0; k < 8; k++) {
            float4 a0 = *reinterpret_cast<float4*>(&As[k][ty * 4]);
            float4 a1 = *reinterpret_cast<float4*>(&As[k][64 + ty * 4]);
            float4 b0 = *reinterpret_cast<float4*>(&Bs[k][tx * 4]);
            float4 b1 = *reinterpret_cast<float4*>(&Bs[k][64 + tx * 4]);
            float ar[8] = {a0.x, a0.y, a0.z, a0.w, a1.x, a1.y, a1.z, a1.w};
            float br[8] = {b0.x, b0.y, b0.z, b0.w, b1.x, b1.y, b1.z, b1.w};
            #pragma unroll
            for (int i = 0; i < 8; i++)
                #pragma unroll
                for (int j = 0; j < 8; j++)
                    acc[i][j] = fmaf(ar[i], br[j], acc[i][j]);
        }
        __syncthreads();
    }

    float bcol[8];
    #pragma unroll
    for (int j = 0; j < 4; j++) {
        bcol[j]     = bias[colTile + tx * 4 + j];
        bcol[4 + j] = bias[colTile + 64 + tx * 4 + j];
    }

    #pragma unroll
    for (int i = 0; i < 8; i++) {
        const int r = rowTile + ((i < 4) ? (ty * 4 + i) : (64 + ty * 4 + i - 4));
        if (r >= M) continue;
        if (EDGE) {
            const int src = ei[r];
            const int dst = ei[NE + r];
            #pragma unroll
            for (int jg = 0; jg < 2; jg++) {
                const int c = colTile + jg * 64 + tx * 4;
                float4 hv = *reinterpret_cast<const float4*>(hg + (size_t)src * 256 + c);
                float4 v;
                v.x = fmaxf(acc[i][jg * 4 + 0] + bcol[jg * 4 + 0] + hv.x, 0.f);
                v.y = fmaxf(acc[i][jg * 4 + 1] + bcol[jg * 4 + 1] + hv.y, 0.f);
                v.z = fmaxf(acc[i][jg * 4 + 2] + bcol[jg * 4 + 2] + hv.z, 0.f);
                v.w = fmaxf(acc[i][jg * 4 + 3] + bcol[jg * 4 + 3] + hv.w, 0.f);
                red_add_v4(agg + (size_t)dst * 256 + c, v);
            }
        } else {
            #pragma unroll
            for (int jg = 0; jg < 2; jg++) {
                const int c = colTile + jg * 64 + tx * 4;
                float4 v;
                v.x = acc[i][jg * 4 + 0] + bcol[jg * 4 + 0];
                v.y = acc[i][jg * 4 + 1] + bcol[jg * 4 + 1];
                v.z = acc[i][jg * 4 + 2] + bcol[jg * 4 + 2];
                v.w = acc[i][jg * 4 + 3] + bcol[jg * 4 + 3];
                if (RELU) {
                    v.x = fmaxf(v.x, 0.f); v.y = fmaxf(v.y, 0.f);
                    v.z = fmaxf(v.z, 0.f); v.w = fmaxf(v.w, 0.f);
                }
                *reinterpret_cast<float4*>(C + (size_t)r * 256 + c) = v;
            }
        }
    }
}

// One block (64 threads) per node: scatter mean-pool contributions.
__global__ void pool_kernel(const float* __restrict__ h,
                            const int* __restrict__ batch,
                            float* __restrict__ pool, float* __restrict__ cnt)
{
    const int node = blockIdx.x;
    const int g = batch[node];
    const int t = threadIdx.x;  // 0..63
    float4 v = *reinterpret_cast<const float4*>(h + (size_t)node * 256 + t * 4);
    red_add_v4(pool + (size_t)g * 256 + t * 4, v);
    if (t == 0) atomicAdd(cnt + g, 1.0f);
}

// One block per graph: mean -> relu(g@W1+b1)@W2+b2 -> L2 normalize.
__global__ void final_kernel(const float* __restrict__ pool,
                             const float* __restrict__ cnt,
                             const float* __restrict__ W1, const float* __restrict__ b1,
                             const float* __restrict__ W2, const float* __restrict__ b2,
                             float* __restrict__ out)
{
    const int g = blockIdx.x;
    const int j = threadIdx.x;  // 0..255
    __shared__ float s[256];
    __shared__ float s2[256];
    __shared__ float redbuf[8];
    __shared__ float snorm;

    const float inv = 1.0f / fmaxf(cnt[g], 1.0f);
    s[j] = pool[g * 256 + j] * inv;
    __syncthreads();

    float t = b1[j];
    #pragma unroll 8
    for (int k = 0; k < 256; k++) t = fmaf(s[k], W1[k * 256 + j], t);
    t = fmaxf(t, 0.f);
    s2[j] = t;
    __syncthreads();

    float o = b2[j];
    #pragma unroll 8
    for (int k = 0; k < 256; k++) o = fmaf(s2[k], W2[k * 256 + j], o);

    float sq = o * o;
    #pragma unroll
    for (int off = 16; off > 0; off >>= 1)
        sq += __shfl_down_sync(0xffffffffu, sq, off);
    if ((j & 31) == 0) redbuf[j >> 5] = sq;
    __syncthreads();
    if (j == 0) {
        float ss = 0.f;
        #pragma unroll
        for (int w = 0; w < 8; w++) ss += redbuf[w];
        snorm = fmaxf(sqrtf(ss), 1e-12f);
    }
    __syncthreads();

    out[g * 256 + j] = o / snorm;
}

extern "C" void kernel_launch(void* const* d_in, const int* in_sizes, int n_in,
                              void* d_out, int out_size)
{
    const float* x   = (const float*)d_in[0];
    const int*   ei  = (const int*)  d_in[1];
    const float* ea  = (const float*)d_in[2];
    const int*   bi  = (const int*)  d_in[3];
    const float* xW  = (const float*)d_in[4];
    const float* xb  = (const float*)d_in[5];
    const float* eW  = (const float*)d_in[6];
    const float* eb  = (const float*)d_in[7];
    const float* W1  = (const float*)d_in[8];
    const float* b1  = (const float*)d_in[9];
    const float* W2  = (const float*)d_in[10];
    const float* b2  = (const float*)d_in[11];
    const float* oW1 = (const float*)d_in[12];
    const float* ob1 = (const float*)d_in[13];
    const float* oW2 = (const float*)d_in[14];
    const float* ob2 = (const float*)d_in[15];
    float* out = (float*)d_out;

    float *ph, *pagg, *pt, *ppool, *pcnt;
    cudaGetSymbolAddress((void**)&ph,    g_h);
    cudaGetSymbolAddress((void**)&pagg,  g_agg);
    cudaGetSymbolAddress((void**)&pt,    g_t);
    cudaGetSymbolAddress((void**)&ppool, g_pool);
    cudaGetSymbolAddress((void**)&pcnt,  g_cnt);

    dim3 gNode(2, (NN + 127) / 128);   // (2, 157)
    dim3 gEdge(2, NE / 128);           // (2, 2500)

    // h = x @ xproj_W + xproj_b
    gemm128<false, false, false><<<gNode, 256>>>(
        x, nullptr, xW, xb, ph, nullptr, nullptr, nullptr, NN, 128);

    for (int l = 0; l < 3; l++) {
        // agg = 0
        zero4<<<(NN * HID / 4 + 255) / 256, 256>>>((float4*)pagg, NN * HID / 4);
        // fused: proj = ea @ eW[l] + eb[l]; msg = relu(h[src] + proj); agg[dst] += msg
        gemm128<false, false, true><<<gEdge, 256>>>(
            ea, nullptr, eW + l * 64 * 256, eb + l * 256,
            nullptr, ei, ph, pagg, NE, 64);
        // t = relu((h + agg) @ W1 + b1)
        gemm128<true, true, false><<<gNode, 256>>>(
            ph, pagg, W1 + l * 256 * 256, b1 + l * 256, pt,
            nullptr, nullptr, nullptr, NN, 256);
        // h = relu(t @ W2 + b2)
        gemm128<true, false, false><<<gNode, 256>>>(
            pt, nullptr, W2 + l * 256 * 256, b2 + l * 256, ph,
            nullptr, nullptr, nullptr, NN, 256);
    }

    // mean pool
    zero4<<<(NN * HID / 4 + 255) / 256, 256>>>((float4*)pagg, NG * HID / 4); // dummy-safe no-op? (see below)
    zero4<<<(NG * HID / 4 + 255) / 256, 256>>>((float4*)ppool, NG * HID / 4);
    zero4<<<1, 256>>>((float4*)pcnt, NG / 4);
    pool_kernel<<<NN, 64>>>(ph, bi, ppool, pcnt);

    // graph head + normalize
    final_kernel<<<NG, 256>>>(ppool, pcnt, oW1, ob1, oW2, ob2, out);
}